// round 7
// baseline (speedup 1.0000x reference)
#include <cuda_runtime.h>

// Uniform cubic B-spline via per-interval monomial (Horner) form. (R5 math.)
// t = (x+1)*31.5, j = trunc(t) clamped to 62, u = t-j,
// out = p0[j] + u*(p1[j] + u*(p2[j] + u*p3[j])).
// Shared table replicated 8x across the eight 16B bank groups: every LDS.128
// quarter-warp phase is conflict-free for random j.
// R7: realized MLP=4 (two contiguous float4 pairs), 6 CTAs/SM so ptxas has
// ~42 registers to keep 4 loads independent.

#define REP 8
#define NTBL 63

__device__ __forceinline__ float eval_one(float x, const float4* __restrict__ tp) {
    float t = fmaf(x, 31.5f, 31.5f);
    int j = (int)t;                  // t >= 0: truncation == floor
    j = min(j, 62);
    float u = t - (float)j;
    float4 p = tp[j * REP];          // tp pre-offset by lane's bank-group
    return fmaf(fmaf(fmaf(p.w, u, p.z), u, p.y), u, p.x);
}

__device__ __forceinline__ float4 eval_four(float4 xv, const float4* __restrict__ tp) {
    float4 ov;
    ov.x = eval_one(xv.x, tp);
    ov.y = eval_one(xv.y, tp);
    ov.z = eval_one(xv.z, tp);
    ov.w = eval_one(xv.w, tp);
    return ov;
}

__global__ void __launch_bounds__(256, 6)
bspline_kernel(const float4* __restrict__ x4,
               const float* __restrict__ coeffs,
               float4* __restrict__ o4, int n2) {
    // n2 = number of float4 PAIRS (n4/2)
    __shared__ float4 tbl[NTBL * REP];
    int tid = threadIdx.x;
    #pragma unroll
    for (int e = tid; e < NTBL * REP; e += 256) {
        int j = e >> 3;
        float c0 = __ldg(coeffs + j);
        float c1 = __ldg(coeffs + j + 1);
        float c2 = __ldg(coeffs + j + 2);
        float c3 = __ldg(coeffs + j + 3);
        float4 p;
        p.x = fmaf(4.0f, c1, c0 + c2) * 0.16666666666666666f;
        p.y = (c2 - c0) * 0.5f;
        p.z = fmaf(-2.0f, c1, c0 + c2) * 0.5f;
        p.w = fmaf(3.0f, c1 - c2, c3 - c0) * 0.16666666666666666f;
        tbl[e] = p;
    }
    __syncthreads();

    const float4* __restrict__ tp = tbl + (tid & (REP - 1));
    const int stride = gridDim.x * blockDim.x;
    int k = blockIdx.x * blockDim.x + tid;

    // Main loop: 4 independent LDG.128 in flight (two contiguous pairs).
    for (; k + stride < n2; k += 2 * stride) {
        int a = 2 * k;
        int b = 2 * (k + stride);
        float4 xa0 = x4[a];
        float4 xa1 = x4[a + 1];
        float4 xb0 = x4[b];
        float4 xb1 = x4[b + 1];
        float4 oa0 = eval_four(xa0, tp);
        float4 oa1 = eval_four(xa1, tp);
        float4 ob0 = eval_four(xb0, tp);
        float4 ob1 = eval_four(xb1, tp);
        o4[a]     = oa0;
        o4[a + 1] = oa1;
        o4[b]     = ob0;
        o4[b + 1] = ob1;
    }
    if (k < n2) {
        int a = 2 * k;
        float4 xa0 = x4[a];
        float4 xa1 = x4[a + 1];
        o4[a]     = eval_four(xa0, tp);
        o4[a + 1] = eval_four(xa1, tp);
    }
}

extern "C" void kernel_launch(void* const* d_in, const int* in_sizes, int n_in,
                              void* d_out, int out_size) {
    const float* x      = (const float*)d_in[0];
    const float* coeffs = (const float*)d_in[1];
    float* out = (float*)d_out;
    int n  = in_sizes[0];
    int n2 = n >> 3;                 // float4 pairs; N = 2^22 divisible by 8
    int threads = 256;
    int blocks  = 888;               // 6 CTAs/SM x 148 SMs = one exact wave
    int max_blocks = (n2 + threads - 1) / threads;
    if (blocks > max_blocks) blocks = max_blocks;
    if (blocks < 1) blocks = 1;
    bspline_kernel<<<blocks, threads>>>((const float4*)x, coeffs, (float4*)out, n2);
}